// round 4
// baseline (speedup 1.0000x reference)
#include <cuda_runtime.h>

#define B_   2
#define H_   56
#define W_   56
#define C_   256
#define NH_  8
#define HD_  32
#define KW_  7
#define NPIX (B_*H_*W_)          // 6272
#define ATTN_ELEMS (B_*NH_*H_*W_*KW_*KW_)   // 2458624
#define OUT_ELEMS  (NPIX*C_)                // 1605632
#define SCALE 0.17677669529663687f          // 1/sqrt(32)

// ---- scratch (no allocations allowed) ----
__device__ float g_q [NPIX*C_];
__device__ float g_k [NPIX*C_];
__device__ float g_v [NPIX*C_];
__device__ float g_ao[NPIX*C_];
__device__ float g_attn_dummy[ATTN_ELEMS];

// ======================================================================
// GEMM 1: fused QKV.  Out[n, j] = sum_k x[n,k] * Wcat[j,k],  j in [0,768)
//   j <  256 -> q (scaled), 256..511 -> k, 512..767 -> v
// 64x64x16 tiles, 256 threads, 4x4 per-thread register tile.
// ======================================================================
__global__ void __launch_bounds__(256) gemm_qkv(
    const float* __restrict__ x,
    const float* __restrict__ w_qk,
    const float* __restrict__ w_v)
{
    __shared__ float As[16][64];
    __shared__ float Ws[16][64];

    const int tid = threadIdx.x;
    const int tx  = tid & 15;         // 0..15  (output col quad)
    const int ty  = tid >> 4;         // 0..15  (output row quad)
    const int m0  = blockIdx.x * 64;  // pixel-row tile
    const int j0  = blockIdx.y * 64;  // output-col tile

    // whole 64-wide tile lies inside one weight matrix (boundaries at 256/512)
    const float* Wmat = (j0 < 512) ? (w_qk + (size_t)j0 * C_)
                                   : (w_v  + (size_t)(j0 - 512) * C_);

    const int lr = tid >> 2;   // 0..63
    const int lq = tid & 3;    // 0..3

    float acc[4][4] = {};

    for (int k0 = 0; k0 < C_; k0 += 16) {
        float4 av = *(const float4*)(x    + (size_t)(m0 + lr) * C_ + k0 + lq * 4);
        float4 wv = *(const float4*)(Wmat + (size_t)lr        * C_ + k0 + lq * 4);
        As[lq*4+0][lr] = av.x; As[lq*4+1][lr] = av.y;
        As[lq*4+2][lr] = av.z; As[lq*4+3][lr] = av.w;
        Ws[lq*4+0][lr] = wv.x; Ws[lq*4+1][lr] = wv.y;
        Ws[lq*4+2][lr] = wv.z; Ws[lq*4+3][lr] = wv.w;
        __syncthreads();

        #pragma unroll
        for (int kk = 0; kk < 16; kk++) {
            float4 a = *(const float4*)&As[kk][ty * 4];
            float4 b = *(const float4*)&Ws[kk][tx * 4];
            acc[0][0] += a.x*b.x; acc[0][1] += a.x*b.y; acc[0][2] += a.x*b.z; acc[0][3] += a.x*b.w;
            acc[1][0] += a.y*b.x; acc[1][1] += a.y*b.y; acc[1][2] += a.y*b.z; acc[1][3] += a.y*b.w;
            acc[2][0] += a.z*b.x; acc[2][1] += a.z*b.y; acc[2][2] += a.z*b.z; acc[2][3] += a.z*b.w;
            acc[3][0] += a.w*b.x; acc[3][1] += a.w*b.y; acc[3][2] += a.w*b.z; acc[3][3] += a.w*b.w;
        }
        __syncthreads();
    }

    float* dst; int coff; float sc;
    if (j0 < 256)      { dst = g_q; coff = j0;       sc = SCALE; }
    else if (j0 < 512) { dst = g_k; coff = j0 - 256; sc = 1.0f;  }
    else               { dst = g_v; coff = j0 - 512; sc = 1.0f;  }

    #pragma unroll
    for (int ii = 0; ii < 4; ii++) {
        int n = m0 + ty * 4 + ii;
        float4 o = make_float4(acc[ii][0]*sc, acc[ii][1]*sc, acc[ii][2]*sc, acc[ii][3]*sc);
        *(float4*)&dst[(size_t)n * C_ + coff + tx * 4] = o;
    }
}

// ======================================================================
// Attention: one warp per (pixel, head).  lane = head-dim (HD = 32).
// ======================================================================
__global__ void __launch_bounds__(256) attn_kernel(float* __restrict__ attn_ext, int ext)
{
    const int warp = (blockIdx.x * blockDim.x + threadIdx.x) >> 5;  // 0..50175
    const int lane = threadIdx.x & 31;

    const int h   = warp & 7;
    const int pix = warp >> 3;
    const int j   = pix % W_;
    const int i   = (pix / W_) % H_;
    const int b   = pix / (W_ * H_);

    float* ap = ext ? attn_ext : g_attn_dummy;

    const float qv = g_q[(size_t)pix * C_ + h * HD_ + lane];

    int sh = i - 3; sh = sh < 0 ? 0 : (sh > H_ - KW_ ? H_ - KW_ : sh);
    int sw = j - 3; sw = sw < 0 ? 0 : (sw > W_ - KW_ ? W_ - KW_ : sw);

    // ---- QK^T: 49 logits, distributed 2 per lane (slot0: t<32, slot1: t-32) ----
    float l0 = 0.0f, l1 = -1e30f;
    #pragma unroll
    for (int p = 0; p < KW_; p++) {
        const int rowpix = (b * H_ + sh + p) * W_ + sw;
        #pragma unroll
        for (int q = 0; q < KW_; q++) {
            const int t = p * KW_ + q;
            float prod = qv * g_k[(size_t)(rowpix + q) * C_ + h * HD_ + lane];
            #pragma unroll
            for (int o = 16; o > 0; o >>= 1)
                prod += __shfl_xor_sync(0xffffffffu, prod, o);
            if (t < 32) { if (lane == t)      l0 = prod; }
            else        { if (lane == t - 32) l1 = prod; }
        }
    }

    // ---- softmax over 49 ----
    float m = fmaxf(l0, l1);
    #pragma unroll
    for (int o = 16; o > 0; o >>= 1)
        m = fmaxf(m, __shfl_xor_sync(0xffffffffu, m, o));
    float e0 = __expf(l0 - m);
    float e1 = (lane < 17) ? __expf(l1 - m) : 0.0f;
    float s = e0 + e1;
    #pragma unroll
    for (int o = 16; o > 0; o >>= 1)
        s += __shfl_xor_sync(0xffffffffu, s, o);
    const float inv = 1.0f / s;

    // write attn probabilities: layout (B, NH, H, W, 49)
    const size_t abase = (size_t)(((b * NH_ + h) * H_ + i) * W_ + j) * 49;
    ap[abase + lane] = e0 * inv;
    if (lane < 17) ap[abase + 32 + lane] = e1 * inv;

    // ---- AV ----
    float acc = 0.0f;
    #pragma unroll
    for (int p = 0; p < KW_; p++) {
        const int rowpix = (b * H_ + sh + p) * W_ + sw;
        #pragma unroll
        for (int q = 0; q < KW_; q++) {
            const int t = p * KW_ + q;
            float a = (t < 32) ? __shfl_sync(0xffffffffu, e0, t)
                               : __shfl_sync(0xffffffffu, e1, t - 32);
            acc += a * g_v[(size_t)(rowpix + q) * C_ + h * HD_ + lane];
        }
    }
    g_ao[(size_t)pix * C_ + h * HD_ + lane] = acc * inv;
}

// ======================================================================
// GEMM 2: projection.  out[n, j] = sum_k g_ao[n,k] * w_proj[j,k] + b[j]
// ======================================================================
__global__ void __launch_bounds__(256) gemm_proj(
    const float* __restrict__ Wp,
    const float* __restrict__ bias,
    float* __restrict__ out)
{
    __shared__ float As[16][64];
    __shared__ float Ws[16][64];

    const int tid = threadIdx.x;
    const int tx  = tid & 15;
    const int ty  = tid >> 4;
    const int m0  = blockIdx.x * 64;
    const int j0  = blockIdx.y * 64;

    const int lr = tid >> 2;
    const int lq = tid & 3;

    float acc[4][4] = {};

    for (int k0 = 0; k0 < C_; k0 += 16) {
        float4 av = *(const float4*)(g_ao + (size_t)(m0 + lr) * C_ + k0 + lq * 4);
        float4 wv = *(const float4*)(Wp   + (size_t)(j0 + lr) * C_ + k0 + lq * 4);
        As[lq*4+0][lr] = av.x; As[lq*4+1][lr] = av.y;
        As[lq*4+2][lr] = av.z; As[lq*4+3][lr] = av.w;
        Ws[lq*4+0][lr] = wv.x; Ws[lq*4+1][lr] = wv.y;
        Ws[lq*4+2][lr] = wv.z; Ws[lq*4+3][lr] = wv.w;
        __syncthreads();

        #pragma unroll
        for (int kk = 0; kk < 16; kk++) {
            float4 a = *(const float4*)&As[kk][ty * 4];
            float4 b = *(const float4*)&Ws[kk][tx * 4];
            acc[0][0] += a.x*b.x; acc[0][1] += a.x*b.y; acc[0][2] += a.x*b.z; acc[0][3] += a.x*b.w;
            acc[1][0] += a.y*b.x; acc[1][1] += a.y*b.y; acc[1][2] += a.y*b.z; acc[1][3] += a.y*b.w;
            acc[2][0] += a.z*b.x; acc[2][1] += a.z*b.y; acc[2][2] += a.z*b.z; acc[2][3] += a.z*b.w;
            acc[3][0] += a.w*b.x; acc[3][1] += a.w*b.y; acc[3][2] += a.w*b.z; acc[3][3] += a.w*b.w;
        }
        __syncthreads();
    }

    const int colbase = j0 + tx * 4;
    float4 bv = *(const float4*)&bias[colbase];

    #pragma unroll
    for (int ii = 0; ii < 4; ii++) {
        int n = m0 + ty * 4 + ii;
        float4 o = make_float4(acc[ii][0] + bv.x, acc[ii][1] + bv.y,
                               acc[ii][2] + bv.z, acc[ii][3] + bv.w);
        *(float4*)&out[(size_t)n * C_ + colbase] = o;
    }
}

// ======================================================================
extern "C" void kernel_launch(void* const* d_in, const int* in_sizes, int n_in,
                              void* d_out, int out_size)
{
    const float* x      = (const float*)d_in[0];
    const float* w_qk   = (const float*)d_in[1];
    const float* w_v    = (const float*)d_in[2];
    const float* w_proj = (const float*)d_in[3];
    const float* b_proj = (const float*)d_in[4];
    float* out = (float*)d_out;

    const int ext = (out_size >= OUT_ELEMS + ATTN_ELEMS) ? 1 : 0;
    float* attn_ptr = out + OUT_ELEMS;   // used only when ext==1

    gemm_qkv <<<dim3(NPIX / 64, 768 / 64), 256>>>(x, w_qk, w_v);
    attn_kernel<<<(NPIX * NH_ * 32) / 256, 256>>>(attn_ptr, ext);
    gemm_proj<<<dim3(NPIX / 64, C_ / 64), 256>>>(w_proj, b_proj, out);
}

// round 8
// speedup vs baseline: 1.2912x; 1.2912x over previous
#include <cuda_runtime.h>

#define B_   2
#define H_   56
#define W_   56
#define C_   256
#define NH_  8
#define HD_  32
#define KW_  7
#define NPIX (B_*H_*W_)          // 6272
#define ATTN_ELEMS (B_*NH_*H_*W_*KW_*KW_)   // 2458624
#define OUT_ELEMS  (NPIX*C_)                // 1605632
#define SCALE 0.17677669529663687f          // 1/sqrt(32)

// ---- scratch (no allocations allowed) ----
__device__ float g_q [NPIX*C_];
__device__ float g_k [NPIX*C_];
__device__ float g_v [NPIX*C_];
__device__ float g_ao[NPIX*C_];
__device__ float g_attn_dummy[ATTN_ELEMS];

// ======================================================================
// GEMM 1: fused QKV.  Out[n, j] = sum_k x[n,k] * Wcat[j,k],  j in [0,768)
// ======================================================================
__global__ void __launch_bounds__(256) gemm_qkv(
    const float* __restrict__ x,
    const float* __restrict__ w_qk,
    const float* __restrict__ w_v)
{
    __shared__ float As[16][64];
    __shared__ float Ws[16][64];

    const int tid = threadIdx.x;
    const int tx  = tid & 15;
    const int ty  = tid >> 4;
    const int m0  = blockIdx.x * 64;
    const int j0  = blockIdx.y * 64;

    const float* Wmat = (j0 < 512) ? (w_qk + (size_t)j0 * C_)
                                   : (w_v  + (size_t)(j0 - 512) * C_);

    const int lr = tid >> 2;
    const int lq = tid & 3;

    float acc[4][4] = {};

    for (int k0 = 0; k0 < C_; k0 += 16) {
        float4 av = *(const float4*)(x    + (size_t)(m0 + lr) * C_ + k0 + lq * 4);
        float4 wv = *(const float4*)(Wmat + (size_t)lr        * C_ + k0 + lq * 4);
        As[lq*4+0][lr] = av.x; As[lq*4+1][lr] = av.y;
        As[lq*4+2][lr] = av.z; As[lq*4+3][lr] = av.w;
        Ws[lq*4+0][lr] = wv.x; Ws[lq*4+1][lr] = wv.y;
        Ws[lq*4+2][lr] = wv.z; Ws[lq*4+3][lr] = wv.w;
        __syncthreads();

        #pragma unroll
        for (int kk = 0; kk < 16; kk++) {
            float4 a = *(const float4*)&As[kk][ty * 4];
            float4 b = *(const float4*)&Ws[kk][tx * 4];
            acc[0][0] += a.x*b.x; acc[0][1] += a.x*b.y; acc[0][2] += a.x*b.z; acc[0][3] += a.x*b.w;
            acc[1][0] += a.y*b.x; acc[1][1] += a.y*b.y; acc[1][2] += a.y*b.z; acc[1][3] += a.y*b.w;
            acc[2][0] += a.z*b.x; acc[2][1] += a.z*b.y; acc[2][2] += a.z*b.z; acc[2][3] += a.z*b.w;
            acc[3][0] += a.w*b.x; acc[3][1] += a.w*b.y; acc[3][2] += a.w*b.z; acc[3][3] += a.w*b.w;
        }
        __syncthreads();
    }

    float* dst; int coff; float sc;
    if (j0 < 256)      { dst = g_q; coff = j0;       sc = SCALE; }
    else if (j0 < 512) { dst = g_k; coff = j0 - 256; sc = 1.0f;  }
    else               { dst = g_v; coff = j0 - 512; sc = 1.0f;  }

    #pragma unroll
    for (int ii = 0; ii < 4; ii++) {
        int n = m0 + ty * 4 + ii;
        float4 o = make_float4(acc[ii][0]*sc, acc[ii][1]*sc, acc[ii][2]*sc, acc[ii][3]*sc);
        *(float4*)&dst[(size_t)n * C_ + coff + tx * 4] = o;
    }
}

// ======================================================================
// Attention (tiled): one CTA = (batch, head, 8x4 pixel tile).
// K/V halo (<=14x10 pixels x 32 dims) staged in static shared memory.
// warp w handles pixel row r0+w, cols c0..c0+3; lane roles:
//   QK: lane owns logits t=lane and t=lane+32 (loop over d, q bcast via shfl)
//   AV: lane = head-dim d (attn weight bcast via shfl)
// ======================================================================
#define TR 8                 // tile rows
#define TC 4                 // tile cols
#define HR 14                // halo rows  (TR + 6)
#define HC 10                // halo cols  (TC + 6)
#define KSTR 33              // K smem pixel stride (pad -> <=2-way conflicts)

__global__ void __launch_bounds__(256) attn_tile(float* __restrict__ attn_ext, int ext)
{
    __shared__ float ks[HR*HC*KSTR];   // 18480 B
    __shared__ float vs[HR*HC*32];     // 17920 B

    const int c0 = blockIdx.x * TC;
    const int r0 = blockIdx.y * TR;
    const int bh = blockIdx.z;
    const int h  = bh & 7;
    const int b  = bh >> 3;

    const int rb = max(r0 - 3, 0);
    const int rn = min(r0 + TR + 2, H_ - 1) - rb + 1;   // <= 14
    const int cb = max(c0 - 3, 0);
    const int cn = min(c0 + TC + 2, W_ - 1) - cb + 1;   // <= 10

    const int warp = threadIdx.x >> 5;
    const int lane = threadIdx.x & 31;

    float* ap = ext ? attn_ext : g_attn_dummy;

    // ---- fill K/V halo into smem (one pixel per warp per iter, lane = dim) ----
    const int area = rn * cn;
    for (int p = warp; p < area; p += 8) {
        const int plr = p / cn;
        const int plc = p - plr * cn;
        const int pix = (b * H_ + rb + plr) * W_ + cb + plc;
        const size_t ga = (size_t)pix * C_ + h * HD_ + lane;
        const int sp = plr * HC + plc;
        ks[sp * KSTR + lane] = g_k[ga];
        vs[sp * 32   + lane] = g_v[ga];
    }
    __syncthreads();

    // ---- per-warp constants ----
    const int i   = r0 + warp;
    const int shl = min(max(i - 3, 0), H_ - KW_) - rb;        // local window row start
    // hoisted per-lane neighbor offsets (t/7, t%7 depend only on lane)
    const int o0 = (shl + lane / 7) * HC + lane % 7;          // slot0: t = lane
    const int t1 = (lane < 17) ? lane + 32 : 32;              // idle lanes alias t=32 (bcast)
    const int o1 = (shl + t1 / 7) * HC + t1 % 7;

    for (int jj = 0; jj < TC; jj++) {
        const int j   = c0 + jj;
        const int swl = min(max(j - 3, 0), W_ - KW_) - cb;    // local window col start
        const int pix = (b * H_ + i) * W_ + j;
        const int p0  = o0 + swl;
        const int p1  = o1 + swl;

        const float q = g_q[(size_t)pix * C_ + h * HD_ + lane];  // pre-scaled

        // ---- QK: 2 logits per lane ----
        float l0 = 0.0f, l1 = 0.0f;
        #pragma unroll
        for (int d = 0; d < 32; d++) {
            const float qd = __shfl_sync(0xffffffffu, q, d);
            l0 = fmaf(qd, ks[p0 * KSTR + d], l0);
            l1 = fmaf(qd, ks[p1 * KSTR + d], l1);
        }
        if (lane >= 17) l1 = -1e30f;

        // ---- softmax over 49 ----
        float m = fmaxf(l0, l1);
        #pragma unroll
        for (int o = 16; o > 0; o >>= 1)
            m = fmaxf(m, __shfl_xor_sync(0xffffffffu, m, o));
        const float e0 = __expf(l0 - m);
        const float e1 = (lane < 17) ? __expf(l1 - m) : 0.0f;
        float s = e0 + e1;
        #pragma unroll
        for (int o = 16; o > 0; o >>= 1)
            s += __shfl_xor_sync(0xffffffffu, s, o);
        const float inv = 1.0f / s;

        // attn probs: layout (B, NH, H, W, 49)
        const size_t abase = (size_t)(((b * NH_ + h) * H_ + i) * W_ + j) * 49;
        ap[abase + lane] = e0 * inv;
        if (lane < 17) ap[abase + 32 + lane] = e1 * inv;

        // ---- AV: lane = dim, broadcast weights ----
        const int pb = shl * HC + swl;
        float acc = 0.0f;
        #pragma unroll
        for (int t = 0; t < 49; t++) {
            const float a = (t < 32) ? __shfl_sync(0xffffffffu, e0, t)
                                     : __shfl_sync(0xffffffffu, e1, t - 32);
            acc = fmaf(a, vs[(pb + (t / 7) * HC + (t % 7)) * 32 + lane], acc);
        }
        g_ao[(size_t)pix * C_ + h * HD_ + lane] = acc * inv;
    }
}

// ======================================================================
// GEMM 2: projection.  out[n, j] = sum_k g_ao[n,k] * w_proj[j,k] + b[j]
// ======================================================================
__global__ void __launch_bounds__(256) gemm_proj(
    const float* __restrict__ Wp,
    const float* __restrict__ bias,
    float* __restrict__ out)
{
    __shared__ float As[16][64];
    __shared__ float Ws[16][64];

    const int tid = threadIdx.x;
    const int tx  = tid & 15;
    const int ty  = tid >> 4;
    const int m0  = blockIdx.x * 64;
    const int j0  = blockIdx.y * 64;

    const int lr = tid >> 2;
    const int lq = tid & 3;

    float acc[4][4] = {};

    for (int k0 = 0; k0 < C_; k0 += 16) {
        float4 av = *(const float4*)(g_ao + (size_t)(m0 + lr) * C_ + k0 + lq * 4);
        float4 wv = *(const float4*)(Wp   + (size_t)(j0 + lr) * C_ + k0 + lq * 4);
        As[lq*4+0][lr] = av.x; As[lq*4+1][lr] = av.y;
        As[lq*4+2][lr] = av.z; As[lq*4+3][lr] = av.w;
        Ws[lq*4+0][lr] = wv.x; Ws[lq*4+1][lr] = wv.y;
        Ws[lq*4+2][lr] = wv.z; Ws[lq*4+3][lr] = wv.w;
        __syncthreads();

        #pragma unroll
        for (int kk = 0; kk < 16; kk++) {
            float4 a = *(const float4*)&As[kk][ty * 4];
            float4 b = *(const float4*)&Ws[kk][tx * 4];
            acc[0][0] += a.x*b.x; acc[0][1] += a.x*b.y; acc[0][2] += a.x*b.z; acc[0][3] += a.x*b.w;
            acc[1][0] += a.y*b.x; acc[1][1] += a.y*b.y; acc[1][2] += a.y*b.z; acc[1][3] += a.y*b.w;
            acc[2][0] += a.z*b.x; acc[2][1] += a.z*b.y; acc[2][2] += a.z*b.z; acc[2][3] += a.z*b.w;
            acc[3][0] += a.w*b.x; acc[3][1] += a.w*b.y; acc[3][2] += a.w*b.z; acc[3][3] += a.w*b.w;
        }
        __syncthreads();
    }

    const int colbase = j0 + tx * 4;
    float4 bv = *(const float4*)&bias[colbase];

    #pragma unroll
    for (int ii = 0; ii < 4; ii++) {
        int n = m0 + ty * 4 + ii;
        float4 o = make_float4(acc[ii][0] + bv.x, acc[ii][1] + bv.y,
                               acc[ii][2] + bv.z, acc[ii][3] + bv.w);
        *(float4*)&out[(size_t)n * C_ + colbase] = o;
    }
}

// ======================================================================
extern "C" void kernel_launch(void* const* d_in, const int* in_sizes, int n_in,
                              void* d_out, int out_size)
{
    const float* x      = (const float*)d_in[0];
    const float* w_qk   = (const float*)d_in[1];
    const float* w_v    = (const float*)d_in[2];
    const float* w_proj = (const float*)d_in[3];
    const float* b_proj = (const float*)d_in[4];
    float* out = (float*)d_out;

    const int ext = (out_size >= OUT_ELEMS + ATTN_ELEMS) ? 1 : 0;
    float* attn_ptr = out + OUT_ELEMS;   // used only when ext==1

    gemm_qkv <<<dim3(NPIX / 64, 768 / 64), 256>>>(x, w_qk, w_v);
    attn_tile<<<dim3(W_ / TC, H_ / TR, B_ * NH_), 256>>>(attn_ptr, ext);
    gemm_proj<<<dim3(NPIX / 64, C_ / 64), 256>>>(w_proj, b_proj, out);
}

// round 9
// speedup vs baseline: 1.4557x; 1.1274x over previous
#include <cuda_runtime.h>

#define B_   2
#define H_   56
#define W_   56
#define C_   256
#define NH_  8
#define HD_  32
#define KW_  7
#define NPIX (B_*H_*W_)          // 6272
#define ATTN_ELEMS (B_*NH_*H_*W_*KW_*KW_)   // 2458624
#define OUT_ELEMS  (NPIX*C_)                // 1605632
#define SCALE 0.17677669529663687f          // 1/sqrt(32)

// ---- scratch (no allocations allowed) ----
__device__ float g_q [NPIX*C_];
__device__ float g_k [NPIX*C_];
__device__ float g_v [NPIX*C_];
__device__ float g_ao[NPIX*C_];
__device__ float g_attn_dummy[ATTN_ELEMS];

// ======================================================================
// Double-buffered SGEMM core: 128x64 CTA tile, BK=16, 256 threads,
// 8x4 per-thread register tile.  C[n,j] = sum_k A[n,k] * W[j,k]
// A row-major [M, 256], W row-major [N, 256] (both K-contiguous).
// ======================================================================
#define BM 128
#define BN 64
#define BKT 16
#define NKT (C_ / BKT)   // 16 k-tiles

struct GemmFrag { float4 a0, a1, bl; };

__device__ __forceinline__ void gemm_ldg(GemmFrag& f,
    const float* __restrict__ A, const float* __restrict__ Wm,
    int m0, int aRow, int q0, int q1, int bRow, int bQ, int k0)
{
    f.a0 = *(const float4*)(A  + (size_t)(m0 + aRow) * C_ + k0 + q0 * 4);
    f.a1 = *(const float4*)(A  + (size_t)(m0 + aRow) * C_ + k0 + q1 * 4);
    f.bl = *(const float4*)(Wm + (size_t)bRow        * C_ + k0 + bQ * 4);
}

__device__ __forceinline__ void gemm_sts(const GemmFrag& f,
    float As[BKT][BM], float Ws[BKT][BN],
    int aRow, int q0, int q1, int bRow, int bQ)
{
    As[q0*4+0][aRow] = f.a0.x; As[q0*4+1][aRow] = f.a0.y;
    As[q0*4+2][aRow] = f.a0.z; As[q0*4+3][aRow] = f.a0.w;
    As[q1*4+0][aRow] = f.a1.x; As[q1*4+1][aRow] = f.a1.y;
    As[q1*4+2][aRow] = f.a1.z; As[q1*4+3][aRow] = f.a1.w;
    Ws[bQ*4+0][bRow] = f.bl.x; Ws[bQ*4+1][bRow] = f.bl.y;
    Ws[bQ*4+2][bRow] = f.bl.z; Ws[bQ*4+3][bRow] = f.bl.w;
}

__device__ __forceinline__ void gemm_mainloop(
    const float* __restrict__ A, const float* __restrict__ Wm,
    int m0, float acc[8][4],
    float As[2][BKT][BM], float Ws[2][BKT][BN])
{
    const int tid  = threadIdx.x;
    const int tx   = tid & 15;        // col group (4 cols)
    const int ty   = tid >> 4;        // row group (8 rows)
    const int aRow = tid >> 1;        // 0..127
    const int q0   = tid & 1;         // quads q0, q0+2
    const int q1   = (tid & 1) + 2;
    const int bRow = tid >> 2;        // 0..63
    const int bQ   = tid & 3;

    GemmFrag f;
    gemm_ldg(f, A, Wm, m0, aRow, q0, q1, bRow, bQ, 0);
    gemm_sts(f, As[0], Ws[0], aRow, q0, q1, bRow, bQ);
    __syncthreads();

    for (int t = 0; t < NKT; t++) {
        const int buf = t & 1;
        if (t + 1 < NKT)
            gemm_ldg(f, A, Wm, m0, aRow, q0, q1, bRow, bQ, (t + 1) * BKT);

        #pragma unroll
        for (int kk = 0; kk < BKT; kk++) {
            float4 aa0 = *(const float4*)&As[buf][kk][ty * 8];
            float4 aa1 = *(const float4*)&As[buf][kk][ty * 8 + 4];
            float4 bb  = *(const float4*)&Ws[buf][kk][tx * 4];
            const float ar[8] = {aa0.x, aa0.y, aa0.z, aa0.w, aa1.x, aa1.y, aa1.z, aa1.w};
            #pragma unroll
            for (int ii = 0; ii < 8; ii++) {
                acc[ii][0] = fmaf(ar[ii], bb.x, acc[ii][0]);
                acc[ii][1] = fmaf(ar[ii], bb.y, acc[ii][1]);
                acc[ii][2] = fmaf(ar[ii], bb.z, acc[ii][2]);
                acc[ii][3] = fmaf(ar[ii], bb.w, acc[ii][3]);
            }
        }

        if (t + 1 < NKT) {
            gemm_sts(f, As[buf ^ 1], Ws[buf ^ 1], aRow, q0, q1, bRow, bQ);
            __syncthreads();
        }
    }
}

// ======================================================================
// GEMM 1: fused QKV.  j < 256 -> q (scaled), 256..511 -> k, 512..767 -> v
// ======================================================================
__global__ void __launch_bounds__(256) gemm_qkv(
    const float* __restrict__ x,
    const float* __restrict__ w_qk,
    const float* __restrict__ w_v)
{
    __shared__ float As[2][BKT][BM];
    __shared__ float Ws[2][BKT][BN];

    const int m0 = blockIdx.x * BM;
    const int j0 = blockIdx.y * BN;
    const float* Wmat = (j0 < 512) ? (w_qk + (size_t)j0 * C_)
                                   : (w_v  + (size_t)(j0 - 512) * C_);

    float acc[8][4] = {};
    gemm_mainloop(x, Wmat, m0, acc, As, Ws);

    float* dst; int coff; float sc;
    if (j0 < 256)      { dst = g_q; coff = j0;       sc = SCALE; }
    else if (j0 < 512) { dst = g_k; coff = j0 - 256; sc = 1.0f;  }
    else               { dst = g_v; coff = j0 - 512; sc = 1.0f;  }

    const int tx = threadIdx.x & 15;
    const int ty = threadIdx.x >> 4;
    #pragma unroll
    for (int ii = 0; ii < 8; ii++) {
        const int n = m0 + ty * 8 + ii;
        float4 o = make_float4(acc[ii][0]*sc, acc[ii][1]*sc, acc[ii][2]*sc, acc[ii][3]*sc);
        *(float4*)&dst[(size_t)n * C_ + coff + tx * 4] = o;
    }
}

// ======================================================================
// GEMM 2: projection.  out[n, j] = sum_k g_ao[n,k] * w_proj[j,k] + b[j]
// ======================================================================
__global__ void __launch_bounds__(256) gemm_proj(
    const float* __restrict__ Wp,
    const float* __restrict__ bias,
    float* __restrict__ out)
{
    __shared__ float As[2][BKT][BM];
    __shared__ float Ws[2][BKT][BN];

    const int m0 = blockIdx.x * BM;
    const int j0 = blockIdx.y * BN;

    float acc[8][4] = {};
    gemm_mainloop(g_ao, Wp + (size_t)j0 * C_, m0, acc, As, Ws);

    const int tx = threadIdx.x & 15;
    const int ty = threadIdx.x >> 4;
    const int colbase = j0 + tx * 4;
    const float4 bv = *(const float4*)&bias[colbase];

    #pragma unroll
    for (int ii = 0; ii < 8; ii++) {
        const int n = m0 + ty * 8 + ii;
        float4 o = make_float4(acc[ii][0] + bv.x, acc[ii][1] + bv.y,
                               acc[ii][2] + bv.z, acc[ii][3] + bv.w);
        *(float4*)&out[(size_t)n * C_ + colbase] = o;
    }
}

// ======================================================================
// Attention (tiled): one CTA = (batch, head, 8x4 pixel tile).  (unchanged)
// ======================================================================
#define TR 8
#define TC 4
#define HR 14
#define HC 10
#define KSTR 33

__global__ void __launch_bounds__(256) attn_tile(float* __restrict__ attn_ext, int ext)
{
    __shared__ float ks[HR*HC*KSTR];
    __shared__ float vs[HR*HC*32];

    const int c0 = blockIdx.x * TC;
    const int r0 = blockIdx.y * TR;
    const int bh = blockIdx.z;
    const int h  = bh & 7;
    const int b  = bh >> 3;

    const int rb = max(r0 - 3, 0);
    const int rn = min(r0 + TR + 2, H_ - 1) - rb + 1;
    const int cb = max(c0 - 3, 0);
    const int cn = min(c0 + TC + 2, W_ - 1) - cb + 1;

    const int warp = threadIdx.x >> 5;
    const int lane = threadIdx.x & 31;

    float* ap = ext ? attn_ext : g_attn_dummy;

    const int area = rn * cn;
    for (int p = warp; p < area; p += 8) {
        const int plr = p / cn;
        const int plc = p - plr * cn;
        const int pix = (b * H_ + rb + plr) * W_ + cb + plc;
        const size_t ga = (size_t)pix * C_ + h * HD_ + lane;
        const int sp = plr * HC + plc;
        ks[sp * KSTR + lane] = g_k[ga];
        vs[sp * 32   + lane] = g_v[ga];
    }
    __syncthreads();

    const int i   = r0 + warp;
    const int shl = min(max(i - 3, 0), H_ - KW_) - rb;
    const int o0 = (shl + lane / 7) * HC + lane % 7;
    const int t1 = (lane < 17) ? lane + 32 : 32;
    const int o1 = (shl + t1 / 7) * HC + t1 % 7;

    for (int jj = 0; jj < TC; jj++) {
        const int j   = c0 + jj;
        const int swl = min(max(j - 3, 0), W_ - KW_) - cb;
        const int pix = (b * H_ + i) * W_ + j;
        const int p0  = o0 + swl;
        const int p1  = o1 + swl;

        const float q = g_q[(size_t)pix * C_ + h * HD_ + lane];

        float l0 = 0.0f, l1 = 0.0f;
        #pragma unroll
        for (int d = 0; d < 32; d++) {
            const float qd = __shfl_sync(0xffffffffu, q, d);
            l0 = fmaf(qd, ks[p0 * KSTR + d], l0);
            l1 = fmaf(qd, ks[p1 * KSTR + d], l1);
        }
        if (lane >= 17) l1 = -1e30f;

        float m = fmaxf(l0, l1);
        #pragma unroll
        for (int o = 16; o > 0; o >>= 1)
            m = fmaxf(m, __shfl_xor_sync(0xffffffffu, m, o));
        const float e0 = __expf(l0 - m);
        const float e1 = (lane < 17) ? __expf(l1 - m) : 0.0f;
        float s = e0 + e1;
        #pragma unroll
        for (int o = 16; o > 0; o >>= 1)
            s += __shfl_xor_sync(0xffffffffu, s, o);
        const float inv = 1.0f / s;

        const size_t abase = (size_t)(((b * NH_ + h) * H_ + i) * W_ + j) * 49;
        ap[abase + lane] = e0 * inv;
        if (lane < 17) ap[abase + 32 + lane] = e1 * inv;

        const int pb = shl * HC + swl;
        float acc = 0.0f;
        #pragma unroll
        for (int t = 0; t < 49; t++) {
            const float a = (t < 32) ? __shfl_sync(0xffffffffu, e0, t)
                                     : __shfl_sync(0xffffffffu, e1, t - 32);
            acc = fmaf(a, vs[(pb + (t / 7) * HC + (t % 7)) * 32 + lane], acc);
        }
        g_ao[(size_t)pix * C_ + h * HD_ + lane] = acc * inv;
    }
}

// ======================================================================
extern "C" void kernel_launch(void* const* d_in, const int* in_sizes, int n_in,
                              void* d_out, int out_size)
{
    const float* x      = (const float*)d_in[0];
    const float* w_qk   = (const float*)d_in[1];
    const float* w_v    = (const float*)d_in[2];
    const float* w_proj = (const float*)d_in[3];
    const float* b_proj = (const float*)d_in[4];
    float* out = (float*)d_out;

    const int ext = (out_size >= OUT_ELEMS + ATTN_ELEMS) ? 1 : 0;
    float* attn_ptr = out + OUT_ELEMS;   // used only when ext==1

    gemm_qkv <<<dim3(NPIX / BM, 768 / BN), 256>>>(x, w_qk, w_v);
    attn_tile<<<dim3(W_ / TC, H_ / TR, B_ * NH_), 256>>>(attn_ptr, ext);
    gemm_proj<<<dim3(NPIX / BM, C_ / BN), 256>>>(w_proj, b_proj, out);
}

// round 12
// speedup vs baseline: 1.8383x; 1.2629x over previous
#include <cuda_runtime.h>
#include <cstdint>

#define B_   2
#define H_   56
#define W_   56
#define C_   256
#define NH_  8
#define HD_  32
#define KW_  7
#define NPIX (B_*H_*W_)          // 6272
#define ATTN_ELEMS (B_*NH_*H_*W_*KW_*KW_)   // 2458624
#define OUT_ELEMS  (NPIX*C_)                // 1605632
#define SCALE 0.17677669529663687f          // 1/sqrt(32)

// ---- scratch (no allocations allowed) ----
__device__ float g_q [NPIX*C_];
__device__ float g_k [NPIX*C_];
__device__ float g_v [NPIX*C_];
__device__ float g_ao[NPIX*C_];
__device__ float g_attn_dummy[ATTN_ELEMS];

// ======================================================================
// TF32 tensor-core GEMM core (mma.sync.m16n8k8).
//   C[m,n] = sum_k A[m,k] * W[n,k]   (A:[M,256], W:[N,256], k-contiguous)
// CTA tile 128x64, BK=16, 256 threads (8 warps, each 32x32 = 2x4 m16n8k8).
// Smem holds tf32-converted data in FRAGMENT layout:
//   A tile : [mblk(8)][kblk(2)][lane(32)][reg(4)]  (uint4 per lane)
//   B tile : [nblk(8)][kblk(2)][lane(32)][reg(2)]  (uint2 per lane)
// Fragment mapping (g=lane>>2, t4=lane&3):
//   A reg: a0=(g,t4) a1=(g+8,t4) a2=(g,t4+4) a3=(g+8,t4+4)
//   B reg: b0=(k=t4,n=g) b1=(k=t4+4,n=g)
//   C reg: c0=(g,2t4) c1=(g,2t4+1) c2=(g+8,2t4) c3=(g+8,2t4+1)
// ======================================================================
#define BM 128
#define BN 64
#define BKT 16
#define NKT (C_ / BKT)       // 16 k-tiles
#define A_STRIDE 2048        // uints per A buffer (8*2*32*4)
#define B_STRIDE 1024        // uints per B buffer (8*2*32*2)

__device__ __forceinline__ unsigned f2tf(float f) {
    unsigned u; asm("cvt.rna.tf32.f32 %0, %1;" : "=r"(u) : "f"(f)); return u;
}

__device__ __forceinline__ void mma_tf32(float c[4], const uint4& a, const uint2& b) {
    asm volatile(
        "mma.sync.aligned.m16n8k8.row.col.f32.tf32.tf32.f32 "
        "{%0,%1,%2,%3}, {%4,%5,%6,%7}, {%8,%9}, {%0,%1,%2,%3};"
        : "+f"(c[0]), "+f"(c[1]), "+f"(c[2]), "+f"(c[3])
        : "r"(a.x), "r"(a.y), "r"(a.z), "r"(a.w), "r"(b.x), "r"(b.y));
}

// scatter one A float4 (row ar, tile-k kk..kk+3) into fragment layout
__device__ __forceinline__ void sts_a(unsigned* As, int ar, int kk, float4 v) {
    const int mblk = ar >> 4;
    const int kblk = kk >> 3;
    const int reg  = ((ar >> 3) & 1) + 2 * ((kk >> 2) & 1);
    const int base = ((mblk * 2 + kblk) * 32 + (ar & 7) * 4) * 4 + reg;
    As[base]      = f2tf(v.x);
    As[base + 4]  = f2tf(v.y);
    As[base + 8]  = f2tf(v.z);
    As[base + 12] = f2tf(v.w);
}

// scatter one B float4 (row bn, tile-k kk..kk+3)
__device__ __forceinline__ void sts_b(unsigned* Bs, int bn, int kk, float4 v) {
    const int nblk = bn >> 3;
    const int kblk = kk >> 3;
    const int reg  = (kk >> 2) & 1;
    const int base = ((nblk * 2 + kblk) * 32 + (bn & 7) * 4) * 2 + reg;
    Bs[base]     = f2tf(v.x);
    Bs[base + 2] = f2tf(v.y);
    Bs[base + 4] = f2tf(v.z);
    Bs[base + 6] = f2tf(v.w);
}

__device__ __forceinline__ void mma_mainloop(
    const float* __restrict__ A, const float* __restrict__ Wm,
    int m0, float acc[2][4][4],
    unsigned* AsS, unsigned* BsS)    // [2][A_STRIDE], [2][B_STRIDE]
{
    const int tid    = threadIdx.x;
    const int lane   = tid & 31;
    const int warp   = tid >> 5;
    const int warp_m = warp & 3;      // 4 m-groups of 32 rows
    const int warp_n = warp >> 2;     // 2 n-groups of 32 cols

    // stager roles
    const int ar  = tid >> 1;               // A row 0..127
    const int ak0 = (tid & 1) * 4;          // A k-offsets ak0, ak0+8
    const int bn  = tid >> 2;               // B row 0..63
    const int bk  = (tid & 3) * 4;          // B k-offset

    const float* Arow = A  + (size_t)(m0 + ar) * C_;
    const float* Brow = Wm + (size_t)bn * C_;

    float4 la0, la1, lb;

    // prologue: tile 0
    la0 = *(const float4*)(Arow + ak0);
    la1 = *(const float4*)(Arow + ak0 + 8);
    lb  = *(const float4*)(Brow + bk);
    sts_a(AsS, ar, ak0,     la0);
    sts_a(AsS, ar, ak0 + 8, la1);
    sts_b(BsS, bn, bk,      lb);
    __syncthreads();

    for (int t = 0; t < NKT; t++) {
        const int buf = t & 1;
        if (t + 1 < NKT) {
            const int k0 = (t + 1) * BKT;
            la0 = *(const float4*)(Arow + k0 + ak0);
            la1 = *(const float4*)(Arow + k0 + ak0 + 8);
            lb  = *(const float4*)(Brow + k0 + bk);
        }

        const uint4* As4 = (const uint4*)(AsS + buf * A_STRIDE);
        const uint2* Bs2 = (const uint2*)(BsS + buf * B_STRIDE);

        #pragma unroll
        for (int kb = 0; kb < 2; kb++) {
            uint4 af0 = As4[((warp_m * 2 + 0) * 2 + kb) * 32 + lane];
            uint4 af1 = As4[((warp_m * 2 + 1) * 2 + kb) * 32 + lane];
            uint2 bf0 = Bs2[((warp_n * 4 + 0) * 2 + kb) * 32 + lane];
            uint2 bf1 = Bs2[((warp_n * 4 + 1) * 2 + kb) * 32 + lane];
            uint2 bf2 = Bs2[((warp_n * 4 + 2) * 2 + kb) * 32 + lane];
            uint2 bf3 = Bs2[((warp_n * 4 + 3) * 2 + kb) * 32 + lane];
            mma_tf32(acc[0][0], af0, bf0);
            mma_tf32(acc[0][1], af0, bf1);
            mma_tf32(acc[0][2], af0, bf2);
            mma_tf32(acc[0][3], af0, bf3);
            mma_tf32(acc[1][0], af1, bf0);
            mma_tf32(acc[1][1], af1, bf1);
            mma_tf32(acc[1][2], af1, bf2);
            mma_tf32(acc[1][3], af1, bf3);
        }

        if (t + 1 < NKT) {
            unsigned* Asw = AsS + (buf ^ 1) * A_STRIDE;
            unsigned* Bsw = BsS + (buf ^ 1) * B_STRIDE;
            sts_a(Asw, ar, ak0,     la0);
            sts_a(Asw, ar, ak0 + 8, la1);
            sts_b(Bsw, bn, bk,      lb);
            __syncthreads();
        }
    }
}

// ======================================================================
// GEMM 1: fused QKV.  j < 256 -> q (scaled), 256..511 -> k, 512..767 -> v
// ======================================================================
__global__ void __launch_bounds__(256) gemm_qkv(
    const float* __restrict__ x,
    const float* __restrict__ w_qk,
    const float* __restrict__ w_v)
{
    __shared__ unsigned As[2 * A_STRIDE];
    __shared__ unsigned Bs[2 * B_STRIDE];

    const int m0 = blockIdx.x * BM;
    const int j0 = blockIdx.y * BN;
    const float* Wmat = (j0 < 512) ? (w_qk + (size_t)j0 * C_)
                                   : (w_v  + (size_t)(j0 - 512) * C_);

    float acc[2][4][4] = {};
    mma_mainloop(x, Wmat, m0, acc, As, Bs);

    float* dst; int coff; float sc;
    if (j0 < 256)      { dst = g_q; coff = j0;       sc = SCALE; }
    else if (j0 < 512) { dst = g_k; coff = j0 - 256; sc = 1.0f;  }
    else               { dst = g_v; coff = j0 - 512; sc = 1.0f;  }

    const int lane = threadIdx.x & 31;
    const int warp = threadIdx.x >> 5;
    const int g  = lane >> 2;
    const int t4 = lane & 3;

    #pragma unroll
    for (int i = 0; i < 2; i++) {
        #pragma unroll
        for (int j = 0; j < 4; j++) {
            const int row = m0 + (warp & 3) * 32 + i * 16 + g;
            const int col = coff + (warp >> 2) * 32 + j * 8 + t4 * 2;
            *(float2*)&dst[(size_t)row * C_ + col] =
                make_float2(acc[i][j][0] * sc, acc[i][j][1] * sc);
            *(float2*)&dst[(size_t)(row + 8) * C_ + col] =
                make_float2(acc[i][j][2] * sc, acc[i][j][3] * sc);
        }
    }
}

// ======================================================================
// GEMM 2: projection.  out[n, j] = sum_k g_ao[n,k] * w_proj[j,k] + b[j]
// ======================================================================
__global__ void __launch_bounds__(256) gemm_proj(
    const float* __restrict__ Wp,
    const float* __restrict__ bias,
    float* __restrict__ out)
{
    __shared__ unsigned As[2 * A_STRIDE];
    __shared__ unsigned Bs[2 * B_STRIDE];

    const int m0 = blockIdx.x * BM;
    const int j0 = blockIdx.y * BN;

    float acc[2][4][4] = {};
    mma_mainloop(g_ao, Wp + (size_t)j0 * C_, m0, acc, As, Bs);

    const int lane = threadIdx.x & 31;
    const int warp = threadIdx.x >> 5;
    const int g  = lane >> 2;
    const int t4 = lane & 3;

    #pragma unroll
    for (int i = 0; i < 2; i++) {
        #pragma unroll
        for (int j = 0; j < 4; j++) {
            const int row = m0 + (warp & 3) * 32 + i * 16 + g;
            const int col = j0 + (warp >> 2) * 32 + j * 8 + t4 * 2;
            const float2 bv = *(const float2*)&bias[col];
            *(float2*)&out[(size_t)row * C_ + col] =
                make_float2(acc[i][j][0] + bv.x, acc[i][j][1] + bv.y);
            *(float2*)&out[(size_t)(row + 8) * C_ + col] =
                make_float2(acc[i][j][2] + bv.x, acc[i][j][3] + bv.y);
        }
    }
}

// ======================================================================
// Attention (tiled): one CTA = (batch, head, 8x4 pixel tile).  (unchanged)
// ======================================================================
#define TR 8
#define TC 4
#define HR 14
#define HC 10
#define KSTR 33

__global__ void __launch_bounds__(256) attn_tile(float* __restrict__ attn_ext, int ext)
{
    __shared__ float ks[HR*HC*KSTR];
    __shared__ float vs[HR*HC*32];

    const int c0 = blockIdx.x * TC;
    const int r0 = blockIdx.y * TR;
    const int bh = blockIdx.z;
    const int h  = bh & 7;
    const int b  = bh >> 3;

    const int rb = max(r0 - 3, 0);
    const int rn = min(r0 + TR + 2, H_ - 1) - rb + 1;
    const int cb = max(c0 - 3, 0);
    const int cn = min(c0 + TC + 2, W_ - 1) - cb + 1;

    const int warp = threadIdx.x >> 5;
    const int lane = threadIdx.x & 31;

    float* ap = ext ? attn_ext : g_attn_dummy;

    const int area = rn * cn;
    for (int p = warp; p < area; p += 8) {
        const int plr = p / cn;
        const int plc = p - plr * cn;
        const int pix = (b * H_ + rb + plr) * W_ + cb + plc;
        const size_t ga = (size_t)pix * C_ + h * HD_ + lane;
        const int sp = plr * HC + plc;
        ks[sp * KSTR + lane] = g_k[ga];
        vs[sp * 32   + lane] = g_v[ga];
    }
    __syncthreads();

    const int i   = r0 + warp;
    const int shl = min(max(i - 3, 0), H_ - KW_) - rb;
    const int o0 = (shl + lane / 7) * HC + lane % 7;
    const int t1 = (lane < 17) ? lane + 32 : 32;
    const int o1 = (shl + t1 / 7) * HC + t1 % 7;

    for (int jj = 0; jj < TC; jj++) {
        const int j   = c0 + jj;
        const int swl = min(max(j - 3, 0), W_ - KW_) - cb;
        const int pix = (b * H_ + i) * W_ + j;
        const int p0  = o0 + swl;
        const int p1  = o1 + swl;

        const float q = g_q[(size_t)pix * C_ + h * HD_ + lane];

        float l0 = 0.0f, l1 = 0.0f;
        #pragma unroll
        for (int d = 0; d < 32; d++) {
            const float qd = __shfl_sync(0xffffffffu, q, d);
            l0 = fmaf(qd, ks[p0 * KSTR + d], l0);
            l1 = fmaf(qd, ks[p1 * KSTR + d], l1);
        }
        if (lane >= 17) l1 = -1e30f;

        float m = fmaxf(l0, l1);
        #pragma unroll
        for (int o = 16; o > 0; o >>= 1)
            m = fmaxf(m, __shfl_xor_sync(0xffffffffu, m, o));
        const float e0 = __expf(l0 - m);
        const float e1 = (lane < 17) ? __expf(l1 - m) : 0.0f;
        float s = e0 + e1;
        #pragma unroll
        for (int o = 16; o > 0; o >>= 1)
            s += __shfl_xor_sync(0xffffffffu, s, o);
        const float inv = 1.0f / s;

        const size_t abase = (size_t)(((b * NH_ + h) * H_ + i) * W_ + j) * 49;
        ap[abase + lane] = e0 * inv;
        if (lane < 17) ap[abase + 32 + lane] = e1 * inv;

        const int pb = shl * HC + swl;
        float acc = 0.0f;
        #pragma unroll
        for (int t = 0; t < 49; t++) {
            const float a = (t < 32) ? __shfl_sync(0xffffffffu, e0, t)
                                     : __shfl_sync(0xffffffffu, e1, t - 32);
            acc = fmaf(a, vs[(pb + (t / 7) * HC + (t % 7)) * 32 + lane], acc);
        }
        g_ao[(size_t)pix * C_ + h * HD_ + lane] = acc * inv;
    }
}

// ======================================================================
extern "C" void kernel_launch(void* const* d_in, const int* in_sizes, int n_in,
                              void* d_out, int out_size)
{
    const float* x      = (const float*)d_in[0];
    const float* w_qk   = (const float*)d_in[1];
    const float* w_v    = (const float*)d_in[2];
    const float* w_proj = (const float*)d_in[3];
    const float* b_proj = (const float*)d_in[4];
    float* out = (float*)d_out;

    const int ext = (out_size >= OUT_ELEMS + ATTN_ELEMS) ? 1 : 0;
    float* attn_ptr = out + OUT_ELEMS;   // used only when ext==1

    gemm_qkv <<<dim3(NPIX / BM, 768 / BN), 256>>>(x, w_qk, w_v);
    attn_tile<<<dim3(W_ / TC, H_ / TR, B_ * NH_), 256>>>(attn_ptr, ext);
    gemm_proj<<<dim3(NPIX / BM, C_ / BN), 256>>>(w_proj, b_proj, out);
}

// round 13
// speedup vs baseline: 1.9419x; 1.0564x over previous
#include <cuda_runtime.h>
#include <cstdint>

#define B_   2
#define H_   56
#define W_   56
#define C_   256
#define NH_  8
#define HD_  32
#define KW_  7
#define NPIX (B_*H_*W_)          // 6272
#define ATTN_ELEMS (B_*NH_*H_*W_*KW_*KW_)   // 2458624
#define OUT_ELEMS  (NPIX*C_)                // 1605632
#define SCALE 0.17677669529663687f          // 1/sqrt(32)

// ---- scratch (no allocations allowed) ----
__device__ float g_q [NPIX*C_];
__device__ float g_k [NPIX*C_];
__device__ float g_v [NPIX*C_];
__device__ float g_ao[NPIX*C_];
__device__ float g_attn_dummy[ATTN_ELEMS];

// ======================================================================
// TF32 tensor-core GEMM core (mma.sync.m16n8k8).
//   C[m,n] = sum_k A[m,k] * W[n,k]   (A:[M,256], W:[N,256], k-contiguous)
// CTA tile 128x64, BK=16, 256 threads (8 warps, each 32x32 = 2x4 m16n8k8).
// Smem holds tf32-converted data in FRAGMENT layout:
//   A tile : [mblk(8)][kblk(2)][lane(32)][reg(4)]  (uint4 per lane)
//   B tile : [nblk(8)][kblk(2)][lane(32)][reg(2)]  (uint2 per lane)
// Fragment mapping (g=lane>>2, t4=lane&3):
//   A reg: a0=(g,t4) a1=(g+8,t4) a2=(g,t4+4) a3=(g+8,t4+4)
//   B reg: b0=(k=t4,n=g) b1=(k=t4+4,n=g)
//   C reg: c0=(g,2t4) c1=(g,2t4+1) c2=(g+8,2t4) c3=(g+8,2t4+1)
// A is staged via a cross-lane 4x4 quad transpose so the store is ONE
// conflict-free STS.128 per pass (the R12 scalar scatter was ~8-16-way
// bank conflicted and made the kernel L1-crossbar-bound).
// ======================================================================
#define BM 128
#define BN 64
#define BKT 16
#define NKT (C_ / BKT)       // 16 k-tiles
#define A_STRIDE 2048        // uints per A buffer (8*2*32*4)
#define B_STRIDE 1024        // uints per B buffer (8*2*32*2)

__device__ __forceinline__ unsigned f2tf(float f) {
    unsigned u; asm("cvt.rna.tf32.f32 %0, %1;" : "=r"(u) : "f"(f)); return u;
}

__device__ __forceinline__ void mma_tf32(float c[4], const uint4& a, const uint2& b) {
    asm volatile(
        "mma.sync.aligned.m16n8k8.row.col.f32.tf32.tf32.f32 "
        "{%0,%1,%2,%3}, {%4,%5,%6,%7}, {%8,%9}, {%0,%1,%2,%3};"
        : "+f"(c[0]), "+f"(c[1]), "+f"(c[2]), "+f"(c[3])
        : "r"(a.x), "r"(a.y), "r"(a.z), "r"(a.w), "r"(b.x), "r"(b.y));
}

// 4x4 transpose across a lane quad (2-stage butterfly, static indices).
// In:  lane q holds row q of a 4x4 matrix M (x0..x3 = M[q][0..3]).
// Out: lane q holds column q (x_j = M[j][q]).
__device__ __forceinline__ void quad_transpose(
    unsigned& x0, unsigned& x1, unsigned& x2, unsigned& x3, int q)
{
    unsigned t;
    t = (q & 1) ? x0 : x1;  t = __shfl_xor_sync(0xffffffffu, t, 1);
    if (q & 1) x0 = t; else x1 = t;
    t = (q & 1) ? x2 : x3;  t = __shfl_xor_sync(0xffffffffu, t, 1);
    if (q & 1) x2 = t; else x3 = t;
    t = (q & 2) ? x0 : x2;  t = __shfl_xor_sync(0xffffffffu, t, 2);
    if (q & 2) x0 = t; else x2 = t;
    t = (q & 2) ? x1 : x3;  t = __shfl_xor_sync(0xffffffffu, t, 2);
    if (q & 2) x1 = t; else x3 = t;
}

// scatter one B float4 (row bn, tile-k kk..kk+3) -- 2-way conflicts, OK
__device__ __forceinline__ void sts_b(unsigned* Bs, int bn, int kk, float4 v) {
    const int nblk = bn >> 3;
    const int kblk = kk >> 3;
    const int reg  = (kk >> 2) & 1;
    const int base = ((nblk * 2 + kblk) * 32 + (bn & 7) * 4) * 2 + reg;
    Bs[base]     = f2tf(v.x);
    Bs[base + 2] = f2tf(v.y);
    Bs[base + 4] = f2tf(v.z);
    Bs[base + 6] = f2tf(v.w);
}

// stage one BK=16 tile: A via quad transpose + STS.128, B via scatter
__device__ __forceinline__ void stage_tile(
    unsigned* Asw, unsigned* Bsw,
    float4 la0, float4 la1, float4 lb,
    int warp, int lane, int q, int bn, int bk)
{
    #pragma unroll
    for (int kb = 0; kb < 2; kb++) {
        float4 v = kb ? la1 : la0;
        unsigned x0 = f2tf(v.x), x1 = f2tf(v.y), x2 = f2tf(v.z), x3 = f2tf(v.w);
        quad_transpose(x0, x1, x2, x3, q);
        ((uint4*)Asw)[(warp * 2 + kb) * 32 + lane] = make_uint4(x0, x1, x2, x3);
    }
    sts_b(Bsw, bn, bk, lb);
}

__device__ __forceinline__ void mma_mainloop(
    const float* __restrict__ A, const float* __restrict__ Wm,
    int m0, float acc[2][4][4],
    unsigned* AsS, unsigned* BsS)    // [2][A_STRIDE], [2][B_STRIDE]
{
    const int tid    = threadIdx.x;
    const int lane   = tid & 31;
    const int warp   = tid >> 5;
    const int warp_m = warp & 3;      // 4 m-groups of 32 rows
    const int warp_n = warp >> 2;     // 2 n-groups of 32 cols

    // A stager roles: warp w covers mblk=w; quad lane roles:
    //   T_q loads (row = w*16 + g + 8*(q&1),  k-quad = kblk*2 + (q>>1))
    const int g    = lane >> 2;
    const int q    = lane & 3;
    const int arow = warp * 16 + g + 8 * (q & 1);
    const int akq4 = ((lane >> 1) & 1) * 4;      // (q>>1)*4

    // B stager roles (unchanged)
    const int bn  = tid >> 2;               // B row 0..63
    const int bk  = (tid & 3) * 4;          // B k-offset

    const float* ArowP = A  + (size_t)(m0 + arow) * C_;
    const float* Brow  = Wm + (size_t)bn * C_;

    float4 la0, la1, lb;

    // prologue: tile 0  (la0: kblk=0, la1: kblk=1)
    la0 = *(const float4*)(ArowP + akq4);
    la1 = *(const float4*)(ArowP + 8 + akq4);
    lb  = *(const float4*)(Brow + bk);
    stage_tile(AsS, BsS, la0, la1, lb, warp, lane, q, bn, bk);
    __syncthreads();

    for (int t = 0; t < NKT; t++) {
        const int buf = t & 1;
        if (t + 1 < NKT) {
            const int k0 = (t + 1) * BKT;
            la0 = *(const float4*)(ArowP + k0 + akq4);
            la1 = *(const float4*)(ArowP + k0 + 8 + akq4);
            lb  = *(const float4*)(Brow + k0 + bk);
        }

        const uint4* As4 = (const uint4*)(AsS + buf * A_STRIDE);
        const uint2* Bs2 = (const uint2*)(BsS + buf * B_STRIDE);

        #pragma unroll
        for (int kb = 0; kb < 2; kb++) {
            uint4 af0 = As4[((warp_m * 2 + 0) * 2 + kb) * 32 + lane];
            uint4 af1 = As4[((warp_m * 2 + 1) * 2 + kb) * 32 + lane];
            uint2 bf0 = Bs2[((warp_n * 4 + 0) * 2 + kb) * 32 + lane];
            uint2 bf1 = Bs2[((warp_n * 4 + 1) * 2 + kb) * 32 + lane];
            uint2 bf2 = Bs2[((warp_n * 4 + 2) * 2 + kb) * 32 + lane];
            uint2 bf3 = Bs2[((warp_n * 4 + 3) * 2 + kb) * 32 + lane];
            mma_tf32(acc[0][0], af0, bf0);
            mma_tf32(acc[0][1], af0, bf1);
            mma_tf32(acc[0][2], af0, bf2);
            mma_tf32(acc[0][3], af0, bf3);
            mma_tf32(acc[1][0], af1, bf0);
            mma_tf32(acc[1][1], af1, bf1);
            mma_tf32(acc[1][2], af1, bf2);
            mma_tf32(acc[1][3], af1, bf3);
        }

        if (t + 1 < NKT) {
            stage_tile(AsS + (buf ^ 1) * A_STRIDE, BsS + (buf ^ 1) * B_STRIDE,
                       la0, la1, lb, warp, lane, q, bn, bk);
            __syncthreads();
        }
    }
}

// ======================================================================
// GEMM 1: fused QKV.  j < 256 -> q (scaled), 256..511 -> k, 512..767 -> v
// ======================================================================
__global__ void __launch_bounds__(256) gemm_qkv(
    const float* __restrict__ x,
    const float* __restrict__ w_qk,
    const float* __restrict__ w_v)
{
    __shared__ unsigned As[2 * A_STRIDE];
    __shared__ unsigned Bs[2 * B_STRIDE];

    const int m0 = blockIdx.x * BM;
    const int j0 = blockIdx.y * BN;
    const float* Wmat = (j0 < 512) ? (w_qk + (size_t)j0 * C_)
                                   : (w_v  + (size_t)(j0 - 512) * C_);

    float acc[2][4][4] = {};
    mma_mainloop(x, Wmat, m0, acc, As, Bs);

    float* dst; int coff; float sc;
    if (j0 < 256)      { dst = g_q; coff = j0;       sc = SCALE; }
    else if (j0 < 512) { dst = g_k; coff = j0 - 256; sc = 1.0f;  }
    else               { dst = g_v; coff = j0 - 512; sc = 1.0f;  }

    const int lane = threadIdx.x & 31;
    const int warp = threadIdx.x >> 5;
    const int g  = lane >> 2;
    const int t4 = lane & 3;

    #pragma unroll
    for (int i = 0; i < 2; i++) {
        #pragma unroll
        for (int j = 0; j < 4; j++) {
            const int row = m0 + (warp & 3) * 32 + i * 16 + g;
            const int col = coff + (warp >> 2) * 32 + j * 8 + t4 * 2;
            *(float2*)&dst[(size_t)row * C_ + col] =
                make_float2(acc[i][j][0] * sc, acc[i][j][1] * sc);
            *(float2*)&dst[(size_t)(row + 8) * C_ + col] =
                make_float2(acc[i][j][2] * sc, acc[i][j][3] * sc);
        }
    }
}

// ======================================================================
// GEMM 2: projection.  out[n, j] = sum_k g_ao[n,k] * w_proj[j,k] + b[j]
// ======================================================================
__global__ void __launch_bounds__(256) gemm_proj(
    const float* __restrict__ Wp,
    const float* __restrict__ bias,
    float* __restrict__ out)
{
    __shared__ unsigned As[2 * A_STRIDE];
    __shared__ unsigned Bs[2 * B_STRIDE];

    const int m0 = blockIdx.x * BM;
    const int j0 = blockIdx.y * BN;

    float acc[2][4][4] = {};
    mma_mainloop(g_ao, Wp + (size_t)j0 * C_, m0, acc, As, Bs);

    const int lane = threadIdx.x & 31;
    const int warp = threadIdx.x >> 5;
    const int g  = lane >> 2;
    const int t4 = lane & 3;

    #pragma unroll
    for (int i = 0; i < 2; i++) {
        #pragma unroll
        for (int j = 0; j < 4; j++) {
            const int row = m0 + (warp & 3) * 32 + i * 16 + g;
            const int col = j0 + (warp >> 2) * 32 + j * 8 + t4 * 2;
            const float2 bv = *(const float2*)&bias[col];
            *(float2*)&out[(size_t)row * C_ + col] =
                make_float2(acc[i][j][0] + bv.x, acc[i][j][1] + bv.y);
            *(float2*)&out[(size_t)(row + 8) * C_ + col] =
                make_float2(acc[i][j][2] + bv.x, acc[i][j][3] + bv.y);
        }
    }
}

// ======================================================================
// Attention (tiled): one CTA = (batch, head, 8x4 pixel tile).  (unchanged)
// ======================================================================
#define TR 8
#define TC 4
#define HR 14
#define HC 10
#define KSTR 33

__global__ void __launch_bounds__(256) attn_tile(float* __restrict__ attn_ext, int ext)
{
    __shared__ float ks[HR*HC*KSTR];
    __shared__ float vs[HR*HC*32];

    const int c0 = blockIdx.x * TC;
    const int r0 = blockIdx.y * TR;
    const int bh = blockIdx.z;
    const int h  = bh & 7;
    const int b  = bh >> 3;

    const int rb = max(r0 - 3, 0);
    const int rn = min(r0 + TR + 2, H_ - 1) - rb + 1;
    const int cb = max(c0 - 3, 0);
    const int cn = min(c0 + TC + 2, W_ - 1) - cb + 1;

    const int warp = threadIdx.x >> 5;
    const int lane = threadIdx.x & 31;

    float* ap = ext ? attn_ext : g_attn_dummy;

    const int area = rn * cn;
    for (int p = warp; p < area; p += 8) {
        const int plr = p / cn;
        const int plc = p - plr * cn;
        const int pix = (b * H_ + rb + plr) * W_ + cb + plc;
        const size_t ga = (size_t)pix * C_ + h * HD_ + lane;
        const int sp = plr * HC + plc;
        ks[sp * KSTR + lane] = g_k[ga];
        vs[sp * 32   + lane] = g_v[ga];
    }
    __syncthreads();

    const int i   = r0 + warp;
    const int shl = min(max(i - 3, 0), H_ - KW_) - rb;
    const int o0 = (shl + lane / 7) * HC + lane % 7;
    const int t1 = (lane < 17) ? lane + 32 : 32;
    const int o1 = (shl + t1 / 7) * HC + t1 % 7;

    for (int jj = 0; jj < TC; jj++) {
        const int j   = c0 + jj;
        const int swl = min(max(j - 3, 0), W_ - KW_) - cb;
        const int pix = (b * H_ + i) * W_ + j;
        const int p0  = o0 + swl;
        const int p1  = o1 + swl;

        const float q = g_q[(size_t)pix * C_ + h * HD_ + lane];

        float l0 = 0.0f, l1 = 0.0f;
        #pragma unroll
        for (int d = 0; d < 32; d++) {
            const float qd = __shfl_sync(0xffffffffu, q, d);
            l0 = fmaf(qd, ks[p0 * KSTR + d], l0);
            l1 = fmaf(qd, ks[p1 * KSTR + d], l1);
        }
        if (lane >= 17) l1 = -1e30f;

        float m = fmaxf(l0, l1);
        #pragma unroll
        for (int o = 16; o > 0; o >>= 1)
            m = fmaxf(m, __shfl_xor_sync(0xffffffffu, m, o));
        const float e0 = __expf(l0 - m);
        const float e1 = (lane < 17) ? __expf(l1 - m) : 0.0f;
        float s = e0 + e1;
        #pragma unroll
        for (int o = 16; o > 0; o >>= 1)
            s += __shfl_xor_sync(0xffffffffu, s, o);
        const float inv = 1.0f / s;

        const size_t abase = (size_t)(((b * NH_ + h) * H_ + i) * W_ + j) * 49;
        ap[abase + lane] = e0 * inv;
        if (lane < 17) ap[abase + 32 + lane] = e1 * inv;

        const int pb = shl * HC + swl;
        float acc = 0.0f;
        #pragma unroll
        for (int t = 0; t < 49; t++) {
            const float a = (t < 32) ? __shfl_sync(0xffffffffu, e0, t)
                                     : __shfl_sync(0xffffffffu, e1, t - 32);
            acc = fmaf(a, vs[(pb + (t / 7) * HC + (t % 7)) * 32 + lane], acc);
        }
        g_ao[(size_t)pix * C_ + h * HD_ + lane] = acc * inv;
    }
}

// ======================================================================
extern "C" void kernel_launch(void* const* d_in, const int* in_sizes, int n_in,
                              void* d_out, int out_size)
{
    const float* x      = (const float*)d_in[0];
    const float* w_qk   = (const float*)d_in[1];
    const float* w_v    = (const float*)d_in[2];
    const float* w_proj = (const float*)d_in[3];
    const float* b_proj = (const float*)d_in[4];
    float* out = (float*)d_out;

    const int ext = (out_size >= OUT_ELEMS + ATTN_ELEMS) ? 1 : 0;
    float* attn_ptr = out + OUT_ELEMS;   // used only when ext==1

    gemm_qkv <<<dim3(NPIX / BM, 768 / BN), 256>>>(x, w_qk, w_v);
    attn_tile<<<dim3(W_ / TC, H_ / TR, B_ * NH_), 256>>>(attn_ptr, ext);
    gemm_proj<<<dim3(NPIX / BM, C_ / BN), 256>>>(w_proj, b_proj, out);
}